// round 10
// baseline (speedup 1.0000x reference)
#include <cuda_runtime.h>
#include <cstdint>

// Problem constants (fixed by setup_inputs)
#define B_   16
#define A_   16
#define T_   14
#define S_   1024
#define S2_  512       // estimated (even) subcarriers
#define SYM0 2
#define SYM1 11

// Expected output: real part only, float32, shape (B, R=1, T, S, A, A)
//   = 58,720,256 floats = 14,680,064 float4 (verified in R3).
#define FULL_N4 14680064u

// cov[b, s, i, j] = 0.5 * sum_{sym in {2,11}} Re( y[b,i,sym,2*(s>>1)] * conj(y[b,j,sym,2*(s>>1)]) )
// broadcast over t (14 copies); s and s+1 share the tile (closest even sc).

// ---------------------------------------------------------------------------
// R10 main variant: compute once into a 4KB smem slab, then broadcast via
// 14 TMA bulk stores (async proxy). Store instructions leave the SM pipe
// entirely; each t-copy is a single monotone 4KB burst.
// ---------------------------------------------------------------------------
__global__ __launch_bounds__(256, 8)
void cov_tma_kernel(const float* __restrict__ y_real,
                    const float* __restrict__ y_imag,
                    float4*      __restrict__ out4)
{
    __shared__ float2 sv[2][2][A_];    // [s2_local][pilot][antenna]
    __shared__ float4 tile[256];       // 4KB slab, exact output order

    const int bid = blockIdx.x;
    const int b   = bid >> 8;                  // batch
    const int p   = bid & 255;                 // s2 pair: s2 = 2p, 2p+1
    const int tid = threadIdx.x;

    // ---- gather: threads 0..63 load 2 s2 x 2 sym x 16 ant complex ----
    if (tid < 64) {
        const int a   = tid & (A_ - 1);
        const int k   = (tid >> 4) & 1;
        const int c   = tid >> 5;              // s2_local 0/1
        const int sym = k ? SYM1 : SYM0;
        const int sc  = 4 * p + 2 * c;         // even subcarrier 2*(2p+c)
        const long off = (((long)(b * A_ + a)) * T_ + sym) * S_ + sc;
        sv[c][k][a] = make_float2(__ldg(y_real + off), __ldg(y_imag + off));
    }
    __syncthreads();

    // ---- compute ONE float4 per thread; tid == sc_local*64 + q ----
    const int q        = tid & 63;
    const int sc_local = tid >> 6;             // 0..3 -> output sc = 4p + sc_local
    const int c        = sc_local >> 1;
    const int i        = q >> 2;
    const int j0       = (q & 3) << 2;

    const float2 vi0 = sv[c][0][i];
    const float2 vi1 = sv[c][1][i];

    float4 val;
    {
        float2 u = sv[c][0][j0 + 0], w = sv[c][1][j0 + 0];
        val.x = 0.5f * (vi0.x * u.x + vi0.y * u.y + vi1.x * w.x + vi1.y * w.y);
        u = sv[c][0][j0 + 1]; w = sv[c][1][j0 + 1];
        val.y = 0.5f * (vi0.x * u.x + vi0.y * u.y + vi1.x * w.x + vi1.y * w.y);
        u = sv[c][0][j0 + 2]; w = sv[c][1][j0 + 2];
        val.z = 0.5f * (vi0.x * u.x + vi0.y * u.y + vi1.x * w.x + vi1.y * w.y);
        u = sv[c][0][j0 + 3]; w = sv[c][1][j0 + 3];
        val.w = 0.5f * (vi0.x * u.x + vi0.y * u.y + vi1.x * w.x + vi1.y * w.y);
    }

    tile[tid] = val;
    __syncthreads();

    // Order generic smem writes before async-proxy reads.
    asm volatile("fence.proxy.async.shared::cta;" ::: "memory");

    // ---- broadcast: 14 TMA bulk stores of the 4KB slab (thread 0) ----
    if (tid == 0) {
        uint32_t s_tile;
        asm("{ .reg .u64 t; cvta.to.shared.u64 t, %1; cvt.u32.u64 %0, t; }"
            : "=r"(s_tile) : "l"(tile));

        // byte offset of slab for t: ((b*T + t)*S + 4p) * 64 float4 * 16B
        const float4* slab0 = out4 + ((size_t)(b * T_) * S_ + 4 * (size_t)p) * 64;
        const size_t t_stride_bytes = (size_t)S_ * 64 * 16;   // 1 MB per t step

#pragma unroll
        for (int t = 0; t < T_; ++t) {
            const char* dst = (const char*)slab0 + (size_t)t * t_stride_bytes;
            asm volatile("cp.async.bulk.global.shared::cta.bulk_group [%0], [%1], %2;"
                         :: "l"(dst), "r"(s_tile), "n"(4096)
                         : "memory");
        }
        asm volatile("cp.async.bulk.commit_group;" ::: "memory");
        // Must complete before block exit (smem is reused by the next block).
        asm volatile("cp.async.bulk.wait_group 0;" ::: "memory");
    }
}

// ---------------------------------------------------------------------------
// Guarded fallback (R9): plain streaming stores with bounds checks. Used only
// if out_size differs from the verified full shape. Cannot fault.
// ---------------------------------------------------------------------------
__global__ __launch_bounds__(256, 8)
void cov_guarded_kernel(const float* __restrict__ y_real,
                        const float* __restrict__ y_imag,
                        float4*      __restrict__ out4,
                        size_t n4)
{
    __shared__ float2 sv[2][2][A_];

    const int bid = blockIdx.x;
    const int b   = bid >> 8;
    const int p   = bid & 255;
    const int tid = threadIdx.x;

    if (tid < 64) {
        const int a   = tid & (A_ - 1);
        const int k   = (tid >> 4) & 1;
        const int c   = tid >> 5;
        const int sym = k ? SYM1 : SYM0;
        const int sc  = 4 * p + 2 * c;
        const long off = (((long)(b * A_ + a)) * T_ + sym) * S_ + sc;
        sv[c][k][a] = make_float2(__ldg(y_real + off), __ldg(y_imag + off));
    }
    __syncthreads();

    const int q        = tid & 63;
    const int sc_local = tid >> 6;
    const int c        = sc_local >> 1;
    const int i        = q >> 2;
    const int j0       = (q & 3) << 2;

    const float2 vi0 = sv[c][0][i];
    const float2 vi1 = sv[c][1][i];

    float4 val;
    {
        float2 u = sv[c][0][j0 + 0], w = sv[c][1][j0 + 0];
        val.x = 0.5f * (vi0.x * u.x + vi0.y * u.y + vi1.x * w.x + vi1.y * w.y);
        u = sv[c][0][j0 + 1]; w = sv[c][1][j0 + 1];
        val.y = 0.5f * (vi0.x * u.x + vi0.y * u.y + vi1.x * w.x + vi1.y * w.y);
        u = sv[c][0][j0 + 2]; w = sv[c][1][j0 + 2];
        val.z = 0.5f * (vi0.x * u.x + vi0.y * u.y + vi1.x * w.x + vi1.y * w.y);
        u = sv[c][0][j0 + 3]; w = sv[c][1][j0 + 3];
        val.w = 0.5f * (vi0.x * u.x + vi0.y * u.y + vi1.x * w.x + vi1.y * w.y);
    }

    size_t idx = ((size_t)(b * T_) * S_ + 4 * (size_t)p + sc_local) * 64 + q;
    const size_t t_stride = (size_t)S_ * 64;

#pragma unroll
    for (int t = 0; t < T_; ++t) {
        if (idx < n4) __stcs(out4 + idx, val);
        idx += t_stride;
    }
}

extern "C" void kernel_launch(void* const* d_in, const int* in_sizes, int n_in,
                              void* d_out, int out_size)
{
    // Identify the two big float arrays (3,670,016 elements each) by size;
    // disambiguate real/imag by input ordering (verified in R3).
    const float* big[2] = {nullptr, nullptr};
    int nbig = 0;
    for (int i = 0; i < n_in; ++i) {
        if (in_sizes[i] > 100000 && nbig < 2) big[nbig++] = (const float*)d_in[i];
    }

    const float* y_real;
    const float* y_imag;
    if (in_sizes[0] > 100000) {
        y_real = big[0]; y_imag = big[1];   // insertion order (verified)
    } else {
        y_imag = big[0]; y_real = big[1];   // alphabetical order
    }

    const size_t n4 = (size_t)out_size / 4;

    if (n4 == (size_t)FULL_N4) {
        cov_tma_kernel<<<B_ * (S2_ / 2), 256>>>(y_real, y_imag, (float4*)d_out);
    } else {
        cov_guarded_kernel<<<B_ * (S2_ / 2), 256>>>(y_real, y_imag,
                                                    (float4*)d_out, n4);
    }
}

// round 11
// speedup vs baseline: 1.1454x; 1.1454x over previous
#include <cuda_runtime.h>
#include <cstdint>

// Problem constants (fixed by setup_inputs)
#define B_   16
#define A_   16
#define T_   14
#define S_   1024
#define S2_  512       // estimated (even) subcarriers
#define SYM0 2
#define SYM1 11

// Expected output: real part only, float32, shape (B, R=1, T, S, A, A)
//   = 58,720,256 floats = 14,680,064 float4 (verified in R3).
#define FULL_N4 14680064u

// cov[b, s, i, j] = 0.5 * sum_{sym in {2,11}} Re( y[b,i,sym,2*(s>>1)] * conj(y[b,j,sym,2*(s>>1)]) )
// broadcast over t (14 copies); s and s+1 share the tile (closest even sc).
//
// R11 = R9 (champion: compute once, guard-free __stcs broadcast) with the
// per-block burst widened 4KB -> 8KB: 2048 blocks x 512 threads, each block
// owns FOUR s2 (8 output subcarrier tiles). Halves the number of concurrent
// write-address streams at the LTS/DRAM schedulers.
template <bool GUARDED>
__global__ __launch_bounds__(512, 4)
void cov_bcast4_kernel(const float* __restrict__ y_real,
                       const float* __restrict__ y_imag,
                       float4*      __restrict__ out4,
                       size_t n4)
{
    __shared__ float2 sv[4][2][A_];   // [s2_local][pilot][antenna]

    const int bid = blockIdx.x;
    const int b   = bid >> 7;                  // / 128 quads
    const int p   = bid & 127;                 // s2 quad index: s2 = 4p .. 4p+3
    const int tid = threadIdx.x;

    // ---- gather: threads 0..127 load 4 s2 x 2 sym x 16 ant complex ----
    if (tid < 128) {
        const int a   = tid & (A_ - 1);
        const int k   = (tid >> 4) & 1;
        const int c   = tid >> 5;              // s2_local 0..3
        const int sym = k ? SYM1 : SYM0;
        const int sc  = 8 * p + 2 * c;         // even subcarrier 2*(4p+c)
        const long off = (((long)(b * A_ + a)) * T_ + sym) * S_ + sc;
        sv[c][k][a] = make_float2(__ldg(y_real + off), __ldg(y_imag + off));
    }
    __syncthreads();

    // ---- compute ONE float4 (4 adjacent j of real cov) per thread ----
    const int q        = tid & 63;             // float4 within one A*A tile
    const int sc_local = tid >> 6;             // 0..7 -> output sc = 8p + sc_local
    const int c        = sc_local >> 1;        // source s2_local 0..3
    const int i        = q >> 2;
    const int j0       = (q & 3) << 2;

    const float2 vi0 = sv[c][0][i];
    const float2 vi1 = sv[c][1][i];

    float4 val;
    {
        float2 u = sv[c][0][j0 + 0], w = sv[c][1][j0 + 0];
        val.x = 0.5f * (vi0.x * u.x + vi0.y * u.y + vi1.x * w.x + vi1.y * w.y);
        u = sv[c][0][j0 + 1]; w = sv[c][1][j0 + 1];
        val.y = 0.5f * (vi0.x * u.x + vi0.y * u.y + vi1.x * w.x + vi1.y * w.y);
        u = sv[c][0][j0 + 2]; w = sv[c][1][j0 + 2];
        val.z = 0.5f * (vi0.x * u.x + vi0.y * u.y + vi1.x * w.x + vi1.y * w.y);
        u = sv[c][0][j0 + 3]; w = sv[c][1][j0 + 3];
        val.w = 0.5f * (vi0.x * u.x + vi0.y * u.y + vi1.x * w.x + vi1.y * w.y);
    }

    // ---- broadcast: 14 streaming stores, 8KB contiguous per block per t ----
    // out float4 index: ((b*T + t)*S + 8p + sc_local) * 64 + q
    size_t idx = ((size_t)(b * T_) * S_ + 8 * (size_t)p + sc_local) * 64 + q;
    const size_t t_stride = (size_t)S_ * 64;

#pragma unroll
    for (int t = 0; t < T_; ++t) {
        if (GUARDED) {
            if (idx < n4) __stcs(out4 + idx, val);
        } else {
            __stcs(out4 + idx, val);           // guard-free pure STG.128 stream
        }
        idx += t_stride;
    }
}

extern "C" void kernel_launch(void* const* d_in, const int* in_sizes, int n_in,
                              void* d_out, int out_size)
{
    // Identify the two big float arrays (3,670,016 elements each) by size;
    // disambiguate real/imag by input ordering (verified in R3).
    const float* big[2] = {nullptr, nullptr};
    int nbig = 0;
    for (int i = 0; i < n_in; ++i) {
        if (in_sizes[i] > 100000 && nbig < 2) big[nbig++] = (const float*)d_in[i];
    }

    const float* y_real;
    const float* y_imag;
    if (in_sizes[0] > 100000) {
        y_real = big[0]; y_imag = big[1];   // insertion order (verified)
    } else {
        y_imag = big[0]; y_real = big[1];   // alphabetical order
    }

    const size_t n4 = (size_t)out_size / 4;

    if (n4 == (size_t)FULL_N4) {
        cov_bcast4_kernel<false><<<B_ * (S2_ / 4), 512>>>(y_real, y_imag,
                                                          (float4*)d_out, n4);
    } else {
        cov_bcast4_kernel<true><<<B_ * (S2_ / 4), 512>>>(y_real, y_imag,
                                                         (float4*)d_out, n4);
    }
}